// round 8
// baseline (speedup 1.0000x reference)
#include <cuda_runtime.h>

#define NCHAN  3
#define H      512
#define W      512
#define KS     21
#define KTAPS  (KS * KS)          // 441

// CTA tile: 128 output cols x 64 output rows, 256 threads = 8 warps.
// thread = (colg, py): colg 0..7 -> 16 cols each; py 0..31 -> rows Yb+2py, +2py+1.
// Input window: rows Yb-10..Yb+73 (84), cols Xb-12..Xb+139 (152 floats, 76 pairs).
#define TROWS  84
#define TPAIRS 80                 // 76 pairs padded for XOR-16 swizzle
#define PLANE  (TROWS * TPAIRS)

typedef unsigned long long ull;

__device__ __forceinline__ void ffma2(ull& d, ull a, ull b) {
    asm("fma.rn.f32x2 %0, %1, %2, %0;" : "+l"(d) : "l"(a), "l"(b));
}
__device__ __forceinline__ ull pk(float lo, float hi) {
    ull r; asm("mov.b64 %0, {%1, %2};" : "=l"(r) : "f"(lo), "f"(hi)); return r;
}
__device__ __forceinline__ void unpk(ull v, float& lo, float& hi) {
    asm("mov.b64 {%0, %1}, %2;" : "=f"(lo), "=f"(hi) : "l"(v));
}

// dynamic smem: [A plane][B plane][kp 484 float2]
#define SMEM_BYTES (2 * PLANE * 8 + 22 * 22 * 8)

__global__ __launch_bounds__(256, 2) void conv_kernel(const float* __restrict__ x,
                                                      const float* __restrict__ d_k,
                                                      float* __restrict__ d_out) {
    extern __shared__ __align__(16) ull sm[];
    ull* smA = sm;
    ull* smB = sm + PLANE;
    float2* kp = reinterpret_cast<float2*>(sm + 2 * PLANE);

    const int tid = threadIdx.x;
    const int img = blockIdx.z;
    const int Xb  = blockIdx.x * 128;
    const int Yb  = blockIdx.y * 64;

    // fused diagonal tap table: kp[r][jj] = (k[r][jj-1], k[r-1][jj]); OOR -> 0
    const float* kptr = d_k + (size_t)(img / NCHAN) * KTAPS;
    for (int i = tid; i < 22 * 22; i += 256) {
        int r  = i / 22;
        int jj = i % 22;
        float lo = (r <= 20 && jj >= 1) ? kptr[r * KS + jj - 1] : 0.f;
        float hi = (r >= 1 && jj <= 20) ? kptr[(r - 1) * KS + jj] : 0.f;
        kp[i] = make_float2(lo, hi);
    }

    // ---- load window into dual swizzled planes (even-only XOR swizzle) ----
    const float* ximg = x + (size_t)img * H * W;
    for (int i = tid; i < TROWS * 38; i += 256) {
        int row = i / 38;                  // 0..83
        int q   = i % 38;                  // quad within 152-float window
        int gy  = Yb - 10 + row;
        int gx  = Xb - 12 + 4 * q;
        bool rok = ((unsigned)gy < H);
        float4 v = make_float4(0.f, 0.f, 0.f, 0.f);
        if (rok && gx >= 0 && gx <= W - 4)
            v = *reinterpret_cast<const float4*>(ximg + (size_t)gy * W + gx);
        float e4 = 0.f;
        int gx4 = gx + 4;
        if (rok && gx4 >= 0 && gx4 < W)
            e4 = ximg[(size_t)gy * W + gx4];

        int sw2  = ((row >> 1) & 7) << 1;
        int base = (2 * q) ^ sw2;          // even slot; pair (base, base+1)
        ull* arow = smA + row * TPAIRS;
        ull* brow = smB + row * TPAIRS;
        *reinterpret_cast<ulonglong2*>(arow + base) =
            make_ulonglong2(pk(v.x, v.y), pk(v.z, v.w));
        *reinterpret_cast<ulonglong2*>(brow + base) =
            make_ulonglong2(pk(v.y, v.z), pk(v.w, e4));
    }
    __syncthreads();

    // ---- main loop: 16 cols x 2 output rows (f32x2 lanes) per thread --------
    const int colg = tid >> 5;            // 8 col groups of 16
    const int py   = tid & 31;            // row pair
    const int p0   = colg * 8;

    ull acc[16];
#pragma unroll
    for (int c = 0; c < 16; ++c) acc[c] = 0ull;

#pragma unroll 1
    for (int r = 0; r < 22; ++r) {
        const int rowi = 2 * py + r;
        const int sw2  = ((rowi >> 1) & 7) << 1;
        const ull* Ar = smA + rowi * TPAIRS;
        const ull* Br = smB + rowi * TPAIRS;

        ull e[20], b[20];
#pragma unroll
        for (int t = 0; t < 10; ++t) {
            int s = (p0 + 2 * t) ^ sw2;
            ulonglong2 va = *reinterpret_cast<const ulonglong2*>(Ar + s);
            ulonglong2 vb = *reinterpret_cast<const ulonglong2*>(Br + s);
            e[2 * t] = va.x; e[2 * t + 1] = va.y;
            b[2 * t] = vb.x; b[2 * t + 1] = vb.y;
        }

        const ulonglong2* kr = reinterpret_cast<const ulonglong2*>(kp + r * 22);
#pragma unroll
        for (int jh = 0; jh < 11; ++jh) {
            ulonglong2 kk = kr[jh];
#pragma unroll
            for (int c = 0; c < 16; ++c) {            // jj = 2jh
                ull a = (c & 1) ? e[jh + (c + 1) / 2] : b[jh + c / 2];
                ffma2(acc[c], a, kk.x);
            }
#pragma unroll
            for (int c = 0; c < 16; ++c) {            // jj = 2jh+1
                ull a = (c & 1) ? b[jh + (c + 1) / 2] : e[jh + c / 2 + 1];
                ffma2(acc[c], a, kk.y);
            }
        }
    }

    // ---- store: 2 rows x 16 cols --------------------------------------------
    float lo[16], hi[16];
#pragma unroll
    for (int c = 0; c < 16; ++c) unpk(acc[c], lo[c], hi[c]);

    float* op = d_out + ((size_t)img * H + Yb + 2 * py) * W + Xb + colg * 16;
#pragma unroll
    for (int j = 0; j < 4; ++j) {
        reinterpret_cast<float4*>(op)[j] =
            make_float4(lo[4 * j], lo[4 * j + 1], lo[4 * j + 2], lo[4 * j + 3]);
        reinterpret_cast<float4*>(op + W)[j] =
            make_float4(hi[4 * j], hi[4 * j + 1], hi[4 * j + 2], hi[4 * j + 3]);
    }
}

extern "C" void kernel_launch(void* const* d_in, const int* in_sizes, int n_in,
                              void* d_out, int out_size) {
    const float* x = (const float*)d_in[0];   // (32,3,512,512) fp32
    const float* k = (const float*)d_in[1];   // (32,1,21,21)  fp32
    float* out = (float*)d_out;

    cudaFuncSetAttribute(conv_kernel,
                         cudaFuncAttributeMaxDynamicSharedMemorySize, SMEM_BYTES);

    dim3 grid(W / 128, H / 64, 96);           // (4, 8, 96)
    conv_kernel<<<grid, 256, SMEM_BYTES>>>(x, k, out);
}

// round 9
// speedup vs baseline: 1.0015x; 1.0015x over previous
#include <cuda_runtime.h>

#define NCHAN  3
#define H      512
#define W      512
#define KS     21
#define KTAPS  (KS * KS)          // 441

// CTA tile: 128 output cols x 64 output rows, 256 threads = 8 warps.
// thread = (colg, py): colg 0..7 -> 16 cols each; py 0..31 -> rows Yb+2py, +2py+1.
// Input window: rows Yb-10..Yb+73 (84), cols Xb-12..Xb+139 (152 floats, 76 pairs).
#define TROWS  84
#define TPAIRS 80                 // 76 pairs padded for XOR-16 swizzle
#define PLANE  (TROWS * TPAIRS)

typedef unsigned long long ull;

__device__ __forceinline__ void ffma2(ull& d, ull a, ull b) {
    asm("fma.rn.f32x2 %0, %1, %2, %0;" : "+l"(d) : "l"(a), "l"(b));
}
__device__ __forceinline__ ull pk(float lo, float hi) {
    ull r; asm("mov.b64 %0, {%1, %2};" : "=l"(r) : "f"(lo), "f"(hi)); return r;
}
__device__ __forceinline__ void unpk(ull v, float& lo, float& hi) {
    asm("mov.b64 {%0, %1}, %2;" : "=f"(lo), "=f"(hi) : "l"(v));
}

// dynamic smem: [A plane][B plane][kp 484 float2]
#define SMEM_BYTES (2 * PLANE * 8 + 22 * 22 * 8)

__global__ __launch_bounds__(256, 2) void conv_kernel(const float* __restrict__ x,
                                                      const float* __restrict__ d_k,
                                                      float* __restrict__ d_out) {
    extern __shared__ __align__(16) ull sm[];
    ull* smA = sm;
    ull* smB = sm + PLANE;
    float2* kp = reinterpret_cast<float2*>(sm + 2 * PLANE);

    const int tid = threadIdx.x;
    const int img = blockIdx.z;
    const int Xb  = blockIdx.x * 128;
    const int Yb  = blockIdx.y * 64;

    // fused diagonal tap table: kp[r][jj] = (k[r][jj-1], k[r-1][jj]); OOR -> 0
    const float* kptr = d_k + (size_t)(img / NCHAN) * KTAPS;
    for (int i = tid; i < 22 * 22; i += 256) {
        int r  = i / 22;
        int jj = i % 22;
        float lo = (r <= 20 && jj >= 1) ? kptr[r * KS + jj - 1] : 0.f;
        float hi = (r >= 1 && jj <= 20) ? kptr[(r - 1) * KS + jj] : 0.f;
        kp[i] = make_float2(lo, hi);
    }

    // ---- load window into dual swizzled planes (even-only XOR swizzle) ----
    const float* ximg = x + (size_t)img * H * W;
    for (int i = tid; i < TROWS * 38; i += 256) {
        int row = i / 38;                  // 0..83
        int q   = i % 38;                  // quad within 152-float window
        int gy  = Yb - 10 + row;
        int gx  = Xb - 12 + 4 * q;
        bool rok = ((unsigned)gy < H);
        float4 v = make_float4(0.f, 0.f, 0.f, 0.f);
        if (rok && gx >= 0 && gx <= W - 4)
            v = *reinterpret_cast<const float4*>(ximg + (size_t)gy * W + gx);
        float e4 = 0.f;
        int gx4 = gx + 4;
        if (rok && gx4 >= 0 && gx4 < W)
            e4 = ximg[(size_t)gy * W + gx4];

        int sw2  = ((row >> 1) & 7) << 1;
        int base = (2 * q) ^ sw2;          // even slot; pair (base, base+1)
        ull* arow = smA + row * TPAIRS;
        ull* brow = smB + row * TPAIRS;
        *reinterpret_cast<ulonglong2*>(arow + base) =
            make_ulonglong2(pk(v.x, v.y), pk(v.z, v.w));
        *reinterpret_cast<ulonglong2*>(brow + base) =
            make_ulonglong2(pk(v.y, v.z), pk(v.w, e4));
    }
    __syncthreads();

    // ---- main loop: 16 cols x 2 output rows (f32x2 lanes) per thread --------
    const int colg = tid >> 5;            // 8 col groups of 16
    const int py   = tid & 31;            // row pair
    const int p0   = colg * 8;

    ull acc[16];
#pragma unroll
    for (int c = 0; c < 16; ++c) acc[c] = 0ull;

#pragma unroll 1
    for (int r = 0; r < 22; ++r) {
        const int rowi = 2 * py + r;
        const int sw2  = ((rowi >> 1) & 7) << 1;
        const ull* Ar = smA + rowi * TPAIRS;
        const ull* Br = smB + rowi * TPAIRS;

        ull e[20], b[20];
#pragma unroll
        for (int t = 0; t < 10; ++t) {
            int s = (p0 + 2 * t) ^ sw2;
            ulonglong2 va = *reinterpret_cast<const ulonglong2*>(Ar + s);
            ulonglong2 vb = *reinterpret_cast<const ulonglong2*>(Br + s);
            e[2 * t] = va.x; e[2 * t + 1] = va.y;
            b[2 * t] = vb.x; b[2 * t + 1] = vb.y;
        }

        const ulonglong2* kr = reinterpret_cast<const ulonglong2*>(kp + r * 22);
#pragma unroll
        for (int jh = 0; jh < 11; ++jh) {
            ulonglong2 kk = kr[jh];
#pragma unroll
            for (int c = 0; c < 16; ++c) {            // jj = 2jh
                ull a = (c & 1) ? e[jh + (c + 1) / 2] : b[jh + c / 2];
                ffma2(acc[c], a, kk.x);
            }
#pragma unroll
            for (int c = 0; c < 16; ++c) {            // jj = 2jh+1
                ull a = (c & 1) ? b[jh + (c + 1) / 2] : e[jh + c / 2 + 1];
                ffma2(acc[c], a, kk.y);
            }
        }
    }

    // ---- store: 2 rows x 16 cols --------------------------------------------
    float lo[16], hi[16];
#pragma unroll
    for (int c = 0; c < 16; ++c) unpk(acc[c], lo[c], hi[c]);

    float* op = d_out + ((size_t)img * H + Yb + 2 * py) * W + Xb + colg * 16;
#pragma unroll
    for (int j = 0; j < 4; ++j) {
        reinterpret_cast<float4*>(op)[j] =
            make_float4(lo[4 * j], lo[4 * j + 1], lo[4 * j + 2], lo[4 * j + 3]);
        reinterpret_cast<float4*>(op + W)[j] =
            make_float4(hi[4 * j], hi[4 * j + 1], hi[4 * j + 2], hi[4 * j + 3]);
    }
}

extern "C" void kernel_launch(void* const* d_in, const int* in_sizes, int n_in,
                              void* d_out, int out_size) {
    const float* x = (const float*)d_in[0];   // (32,3,512,512) fp32
    const float* k = (const float*)d_in[1];   // (32,1,21,21)  fp32
    float* out = (float*)d_out;

    cudaFuncSetAttribute(conv_kernel,
                         cudaFuncAttributeMaxDynamicSharedMemorySize, SMEM_BYTES);

    dim3 grid(W / 128, H / 64, 96);           // (4, 8, 96)
    conv_kernel<<<grid, 256, SMEM_BYTES>>>(x, k, out);
}

// round 10
// speedup vs baseline: 1.1079x; 1.1062x over previous
#include <cuda_runtime.h>

#define NCHAN  3
#define H      512
#define W      512
#define KS     21
#define KTAPS  (KS * KS)          // 441

// CTA tile: 64 output cols x 64 output rows, 128 threads = 4 warps.
// thread = (colg, py): colg 0..3 -> 16 cols; py 0..31 -> output rows Yb+2py, +2py+1.
// Input window: rows Yb-10..Yb+73 (84), cols Xb-12..Xb+75 (88 floats, 44 pairs).
#define TROWS  84
#define TPAIRS 48                 // 44 pairs padded for XOR-16 swizzle
#define PLANE  (TROWS * TPAIRS)

typedef unsigned long long ull;

// Zero-padded per-batch tap table in constant memory:
// ckpad[b][s][dx], s = dy+1 (s=0 and s=22 are zero rows). 32*23*21 floats = 61.8KB.
__constant__ float ckpad[32 * 23 * 21];
__device__   float g_kpad[32 * 23 * 21];   // staging (device-writable)

__device__ __forceinline__ void ffma2(ull& d, ull a, ull b) {
    asm("fma.rn.f32x2 %0, %1, %2, %0;" : "+l"(d) : "l"(a), "l"(b));
}
__device__ __forceinline__ ull pk(float lo, float hi) {
    ull r; asm("mov.b64 %0, {%1, %2};" : "=l"(r) : "f"(lo), "f"(hi)); return r;
}
__device__ __forceinline__ ull dup(float v) {
    ull r; asm("mov.b64 %0, {%1, %1};" : "=l"(r) : "f"(v)); return r;
}
__device__ __forceinline__ void unpk(ull v, float& lo, float& hi) {
    asm("mov.b64 {%0, %1}, %2;" : "=f"(lo), "=f"(hi) : "l"(v));
}

// ---- prep: build zero-padded tap table in device global --------------------
__global__ void prep_kernel(const float* __restrict__ k) {
    int i = blockIdx.x * 256 + threadIdx.x;
    if (i >= 32 * 23 * 21) return;
    int dx = i % 21;
    int s  = (i / 21) % 23;
    int b  = i / (21 * 23);
    float v = 0.f;
    if (s >= 1 && s <= 21) v = k[((size_t)b * 21 + (s - 1)) * 21 + dx];
    g_kpad[i] = v;
}

// dynamic smem: two swizzled pair-planes only (taps come from constant memory)
#define SMEM_BYTES (2 * PLANE * 8)

__global__ __launch_bounds__(128, 3) void conv_kernel(const float* __restrict__ x,
                                                      float* __restrict__ d_out) {
    extern __shared__ __align__(16) ull sm[];
    ull* smA = sm;
    ull* smB = sm + PLANE;

    const int tid = threadIdx.x;
    const int img = blockIdx.z;
    const int Xb  = blockIdx.x * 64;
    const int Yb  = blockIdx.y * 64;

    // ---- load window into dual per-slot-swizzled planes --------------------
    // A pair p: cols (Xb-12+2p, +1); B pair p: cols (Xb-12+2p+1, +2).
    // slot of pair p in row `row` = p ^ ((row>>1)&15); half-swap for 16B stores.
    const float* ximg = x + (size_t)img * H * W;
    for (int i = tid; i < TROWS * 22; i += 128) {
        int row = i / 22;
        int q   = i % 22;
        int gy  = Yb - 10 + row;
        int gx  = Xb - 12 + 4 * q;
        bool rok = ((unsigned)gy < H);
        float4 v = make_float4(0.f, 0.f, 0.f, 0.f);
        if (rok && gx >= 0 && gx <= W - 4)
            v = *reinterpret_cast<const float4*>(ximg + (size_t)gy * W + gx);
        float e4 = 0.f;
        int gx4 = gx + 4;
        if (rok && gx4 >= 0 && gx4 < W)
            e4 = ximg[(size_t)gy * W + gx4];

        int sw   = (row >> 1) & 15;
        int base = (2 * q) ^ (sw & 14);
        ull alo = pk(v.x, v.y), ahi = pk(v.z, v.w);
        ull blo = pk(v.y, v.z), bhi = pk(v.w, e4);
        if (sw & 1) { ull t = alo; alo = ahi; ahi = t; t = blo; blo = bhi; bhi = t; }
        ull* arow = smA + row * TPAIRS;
        ull* brow = smB + row * TPAIRS;
        *reinterpret_cast<ulonglong2*>(arow + base) = make_ulonglong2(alo, ahi);
        *reinterpret_cast<ulonglong2*>(brow + base) = make_ulonglong2(blo, bhi);
    }
    __syncthreads();

    // ---- main loop: 16 cols (8 column-pairs) x 2 rows per thread ------------
    // acc0[i] = (out[y0][X+2i], out[y0][X+2i+1]), acc1[i] = same for y1=y0+1.
    // Input row r (0..21) serves both: out0 with tap row dy=r (slot r+1),
    // out1 with dy=r-1 (slot r). Taps are warp-uniform constant loads.
    const int colg = tid >> 5;
    const int py   = tid & 31;
    const int p0   = colg * 8;

    const float* ck = ckpad + (size_t)(img / NCHAN) * (23 * 21);

    ull acc0[8], acc1[8];
#pragma unroll
    for (int i = 0; i < 8; ++i) { acc0[i] = 0ull; acc1[i] = 0ull; }

#pragma unroll 1
    for (int r = 0; r < 22; ++r) {
        const int rowi = 2 * py + r;
        const int sw   = (rowi >> 1) & 15;
        const ull* Ar = smA + rowi * TPAIRS;
        const ull* Br = smB + rowi * TPAIRS;

        // data pairs for this input row (shared by both output rows):
        // even offsets o=-10..24 -> A pairs p0+1..p0+18
        // odd  offsets o=-9..23  -> B pairs p0+1..p0+17
        ull pe[19], po[18];
#pragma unroll
        for (int j = 1; j <= 18; ++j) pe[j] = Ar[(p0 + j) ^ sw];
#pragma unroll
        for (int j = 1; j <= 17; ++j) po[j] = Br[(p0 + j) ^ sw];

        const float* k1r = ck + r * 21;       // taps for out1 (dy=r-1; slot r)
        const float* k0r = k1r + 21;          // taps for out0 (dy=r;   slot r+1)

#pragma unroll
        for (int dx = 0; dx < 21; ++dx) {
            ull kk0 = dup(k0r[dx]);
            ull kk1 = dup(k1r[dx]);
#pragma unroll
            for (int i = 0; i < 8; ++i) {
                const int o = 2 * i + dx - 10;          // col offset of pair start
                ull a = (o & 1) ? po[(o + 11) >> 1] : pe[(o + 12) >> 1];
                ffma2(acc0[i], a, kk0);
                ffma2(acc1[i], a, kk1);
            }
        }
    }

    // ---- store: 2 rows x 16 contiguous cols ---------------------------------
    float r0[16], r1[16];
#pragma unroll
    for (int i = 0; i < 8; ++i) {
        unpk(acc0[i], r0[2 * i], r0[2 * i + 1]);
        unpk(acc1[i], r1[2 * i], r1[2 * i + 1]);
    }

    float* op = d_out + ((size_t)img * H + Yb + 2 * py) * W + Xb + colg * 16;
#pragma unroll
    for (int j = 0; j < 4; ++j) {
        reinterpret_cast<float4*>(op)[j] =
            make_float4(r0[4 * j], r0[4 * j + 1], r0[4 * j + 2], r0[4 * j + 3]);
        reinterpret_cast<float4*>(op + W)[j] =
            make_float4(r1[4 * j], r1[4 * j + 1], r1[4 * j + 2], r1[4 * j + 3]);
    }
}

extern "C" void kernel_launch(void* const* d_in, const int* in_sizes, int n_in,
                              void* d_out, int out_size) {
    const float* x = (const float*)d_in[0];   // (32,3,512,512) fp32
    const float* k = (const float*)d_in[1];   // (32,1,21,21)  fp32
    float* out = (float*)d_out;

    // 1) build padded tap table in device global, then copy into __constant__
    const int ktot = 32 * 23 * 21;
    prep_kernel<<<(ktot + 255) / 256, 256>>>(k);

    void* kpad_addr = nullptr;
    cudaGetSymbolAddress(&kpad_addr, g_kpad);
    cudaMemcpyToSymbolAsync(ckpad, kpad_addr, ktot * sizeof(float), 0,
                            cudaMemcpyDeviceToDevice, 0);

    // 2) main conv
    cudaFuncSetAttribute(conv_kernel,
                         cudaFuncAttributeMaxDynamicSharedMemorySize, SMEM_BYTES);
    dim3 grid(W / 64, H / 64, 96);            // (8, 8, 96)
    conv_kernel<<<grid, 128, SMEM_BYTES>>>(x, out);
}

// round 11
// speedup vs baseline: 1.1123x; 1.0039x over previous
#include <cuda_runtime.h>

#define NCHAN  3
#define H      512
#define W      512
#define KS     21
#define KTAPS  (KS * KS)          // 441

// CTA tile: 64 output cols x 64 output rows, 128 threads = 4 warps.
// thread = (colg, py): colg 0..3 -> 16 cols; py 0..31 -> output rows Yb+2py, +2py+1.
// Input window: rows Yb-10..Yb+73 (84), cols Xb-12..Xb+75 (88 floats, 44 pairs).
#define TROWS  84
#define TPAIRS 48                 // 44 pairs padded for XOR-16 swizzle
#define PLANE  (TROWS * TPAIRS)

typedef unsigned long long ull;

// Zero-padded per-batch tap table in constant memory:
// ckpad[b][s][dx], s = dy+1 (s=0 and s=22 are zero rows). 32*23*21 floats = 61.8KB.
__constant__ float ckpad[32 * 23 * 21];
__device__   float g_kpad[32 * 23 * 21];   // staging (device-writable)

__device__ __forceinline__ void ffma2(ull& d, ull a, ull b) {
    asm("fma.rn.f32x2 %0, %1, %2, %0;" : "+l"(d) : "l"(a), "l"(b));
}
__device__ __forceinline__ ull pk(float lo, float hi) {
    ull r; asm("mov.b64 %0, {%1, %2};" : "=l"(r) : "f"(lo), "f"(hi)); return r;
}
__device__ __forceinline__ ull dup(float v) {
    ull r; asm("mov.b64 %0, {%1, %1};" : "=l"(r) : "f"(v)); return r;
}
__device__ __forceinline__ void unpk(ull v, float& lo, float& hi) {
    asm("mov.b64 {%0, %1}, %2;" : "=f"(lo), "=f"(hi) : "l"(v));
}

// ---- prep: build zero-padded tap table in device global --------------------
__global__ void prep_kernel(const float* __restrict__ k) {
    int i = blockIdx.x * 256 + threadIdx.x;
    if (i >= 32 * 23 * 21) return;
    int dx = i % 21;
    int s  = (i / 21) % 23;
    int b  = i / (21 * 23);
    float v = 0.f;
    if (s >= 1 && s <= 21) v = k[((size_t)b * 21 + (s - 1)) * 21 + dx];
    g_kpad[i] = v;
}

// dynamic smem: two swizzled pair-planes only (taps come from constant memory)
#define SMEM_BYTES (2 * PLANE * 8)

__global__ __launch_bounds__(128, 3) void conv_kernel(const float* __restrict__ x,
                                                      float* __restrict__ d_out) {
    extern __shared__ __align__(16) ull sm[];
    ull* smA = sm;
    ull* smB = sm + PLANE;

    const int tid = threadIdx.x;
    const int img = blockIdx.z;
    const int Xb  = blockIdx.x * 64;
    const int Yb  = blockIdx.y * 64;

    // ---- load window into dual per-slot-swizzled planes --------------------
    // A pair p: cols (Xb-12+2p, +1); B pair p: cols (Xb-12+2p+1, +2).
    // slot of pair p in row `row` = p ^ ((row>>1)&15); half-swap for 16B stores.
    const float* ximg = x + (size_t)img * H * W;
    for (int i = tid; i < TROWS * 22; i += 128) {
        int row = i / 22;
        int q   = i % 22;
        int gy  = Yb - 10 + row;
        int gx  = Xb - 12 + 4 * q;
        bool rok = ((unsigned)gy < H);
        float4 v = make_float4(0.f, 0.f, 0.f, 0.f);
        if (rok && gx >= 0 && gx <= W - 4)
            v = *reinterpret_cast<const float4*>(ximg + (size_t)gy * W + gx);
        float e4 = 0.f;
        int gx4 = gx + 4;
        if (rok && gx4 >= 0 && gx4 < W)
            e4 = ximg[(size_t)gy * W + gx4];

        int sw   = (row >> 1) & 15;
        int base = (2 * q) ^ (sw & 14);
        ull alo = pk(v.x, v.y), ahi = pk(v.z, v.w);
        ull blo = pk(v.y, v.z), bhi = pk(v.w, e4);
        if (sw & 1) { ull t = alo; alo = ahi; ahi = t; t = blo; blo = bhi; bhi = t; }
        ull* arow = smA + row * TPAIRS;
        ull* brow = smB + row * TPAIRS;
        *reinterpret_cast<ulonglong2*>(arow + base) = make_ulonglong2(alo, ahi);
        *reinterpret_cast<ulonglong2*>(brow + base) = make_ulonglong2(blo, bhi);
    }
    __syncthreads();

    // ---- main loop: 16 cols (8 column-pairs) x 2 rows per thread ------------
    // acc0[i] = (out[y0][X+2i], out[y0][X+2i+1]), acc1[i] = same for y1=y0+1.
    // Input row r (0..21) serves both: out0 with tap row dy=r (slot r+1),
    // out1 with dy=r-1 (slot r). Taps are warp-uniform constant loads.
    const int colg = tid >> 5;
    const int py   = tid & 31;
    const int p0   = colg * 8;

    const float* ck = ckpad + (size_t)(img / NCHAN) * (23 * 21);

    ull acc0[8], acc1[8];
#pragma unroll
    for (int i = 0; i < 8; ++i) { acc0[i] = 0ull; acc1[i] = 0ull; }

#pragma unroll 1
    for (int r = 0; r < 22; ++r) {
        const int rowi = 2 * py + r;
        const int sw   = (rowi >> 1) & 15;
        const ull* Ar = smA + rowi * TPAIRS;
        const ull* Br = smB + rowi * TPAIRS;

        // data pairs for this input row (shared by both output rows):
        // even offsets o=-10..24 -> A pairs p0+1..p0+18
        // odd  offsets o=-9..23  -> B pairs p0+1..p0+17
        ull pe[19], po[18];
#pragma unroll
        for (int j = 1; j <= 18; ++j) pe[j] = Ar[(p0 + j) ^ sw];
#pragma unroll
        for (int j = 1; j <= 17; ++j) po[j] = Br[(p0 + j) ^ sw];

        const float* k1r = ck + r * 21;       // taps for out1 (dy=r-1; slot r)
        const float* k0r = k1r + 21;          // taps for out0 (dy=r;   slot r+1)

#pragma unroll
        for (int dx = 0; dx < 21; ++dx) {
            ull kk0 = dup(k0r[dx]);
            ull kk1 = dup(k1r[dx]);
#pragma unroll
            for (int i = 0; i < 8; ++i) {
                const int o = 2 * i + dx - 10;          // col offset of pair start
                ull a = (o & 1) ? po[(o + 11) >> 1] : pe[(o + 12) >> 1];
                ffma2(acc0[i], a, kk0);
                ffma2(acc1[i], a, kk1);
            }
        }
    }

    // ---- store: 2 rows x 16 contiguous cols ---------------------------------
    float r0[16], r1[16];
#pragma unroll
    for (int i = 0; i < 8; ++i) {
        unpk(acc0[i], r0[2 * i], r0[2 * i + 1]);
        unpk(acc1[i], r1[2 * i], r1[2 * i + 1]);
    }

    float* op = d_out + ((size_t)img * H + Yb + 2 * py) * W + Xb + colg * 16;
#pragma unroll
    for (int j = 0; j < 4; ++j) {
        reinterpret_cast<float4*>(op)[j] =
            make_float4(r0[4 * j], r0[4 * j + 1], r0[4 * j + 2], r0[4 * j + 3]);
        reinterpret_cast<float4*>(op + W)[j] =
            make_float4(r1[4 * j], r1[4 * j + 1], r1[4 * j + 2], r1[4 * j + 3]);
    }
}

extern "C" void kernel_launch(void* const* d_in, const int* in_sizes, int n_in,
                              void* d_out, int out_size) {
    const float* x = (const float*)d_in[0];   // (32,3,512,512) fp32
    const float* k = (const float*)d_in[1];   // (32,1,21,21)  fp32
    float* out = (float*)d_out;

    // 1) build padded tap table in device global, then copy into __constant__
    const int ktot = 32 * 23 * 21;
    prep_kernel<<<(ktot + 255) / 256, 256>>>(k);

    void* kpad_addr = nullptr;
    cudaGetSymbolAddress(&kpad_addr, g_kpad);
    cudaMemcpyToSymbolAsync(ckpad, kpad_addr, ktot * sizeof(float), 0,
                            cudaMemcpyDeviceToDevice, 0);

    // 2) main conv
    cudaFuncSetAttribute(conv_kernel,
                         cudaFuncAttributeMaxDynamicSharedMemorySize, SMEM_BYTES);
    dim3 grid(W / 64, H / 64, 96);            // (8, 8, 96)
    conv_kernel<<<grid, 128, SMEM_BYTES>>>(x, out);
}